// round 14
// baseline (speedup 1.0000x reference)
#include <cuda_runtime.h>
#include <cuda_bf16.h>
#include <math.h>

#define B_ 16
#define S_ 1024
#define D_ 1024
#define R_ (B_*S_)           // 16384 rows (step-major: r = s*16 + b)
#define NR 256               // rows per chunk (16 steps x 16 batch)
#define NCH 64               // chunks
#define NRNR ((long)NR*NR)
#define ETA (0.01f * (2.0f/16384.0f))
#define NB 296               // persistent blocks (2/SM)
#define NT 256
#define SMS 12               // words per plane row (8 used + 4 pad; conflict-free)
#define PLW (128*SMS)        // words per plane = 1536
#define STW (4*PLW)          // words per stage = 6144
#define DSMEM (3*STW*4)      // 73728 bytes: 3-stage pipeline

typedef unsigned short ushort_;

// ---------------- fp32 scratch ----------------
static __device__ float g_b0[R_*D_];        // STATE
static __device__ float g_b1[R_*D_];        // RDbase -> RD
static __device__ float g_W [D_*D_];        // W master
static __device__ float g_ET[D_*R_];        // E0^T (fp32, read in phA epi)
static __device__ float g_Sa[NCH*NR*NR];
static __device__ float g_Sb[NCH*NR*NR];

// ---------------- bf16 hi/lo plane scratch (unsigned = 2 bf16) -------------
static __device__ unsigned g_pHh [R_*D_/2], g_pHl [R_*D_/2];   // H, later H2
static __device__ unsigned g_pWsh[D_*D_/2], g_pWsl[D_*D_/2];
static __device__ unsigned g_pWph[D_*D_/2], g_pWpl[D_*D_/2];
static __device__ unsigned g_pW1h[D_*D_/2], g_pW1l[D_*D_/2];
static __device__ unsigned g_pW2h[D_*D_/2], g_pW2l[D_*D_/2];
static __device__ unsigned g_pWh [D_*D_/2], g_pWl [D_*D_/2];
static __device__ unsigned g_pTVh [R_*D_/2], g_pTVl [R_*D_/2];
static __device__ unsigned g_pTVTh[R_*D_/2], g_pTVTl[R_*D_/2];
static __device__ unsigned g_pSTTh[R_*D_/2], g_pSTTl[R_*D_/2];
static __device__ unsigned g_pPRh [R_*D_/2], g_pPRl [R_*D_/2];
static __device__ unsigned g_pMTh [R_*D_/2], g_pMTl [R_*D_/2];
static __device__ unsigned g_pETh [R_*D_/2], g_pETl [R_*D_/2];
static __device__ unsigned g_pTh  [NCH*NR*NR/2], g_pTl  [NCH*NR*NR/2];
static __device__ unsigned g_pTTh [NCH*NR*NR/2], g_pTTl [NCH*NR*NR/2];
static __device__ unsigned g_pT2h [NCH*NR*NR/2], g_pT2l [NCH*NR*NR/2];
static __device__ unsigned g_pCT2h[NCH*NR*NR/2], g_pCT2l[NCH*NR*NR/2];
static __device__ unsigned g_pSah [NCH*NR*NR/2], g_pSal [NCH*NR*NR/2];
static __device__ unsigned g_pSbh [NCH*NR*NR/2], g_pSbl [NCH*NR*NR/2];
static __device__ unsigned g_pQh  [NCH*NR*NR/2], g_pQl  [NCH*NR*NR/2];

static __device__ unsigned g_bar_cnt;
static __device__ unsigned g_bar_phase;

__global__ void reset_kernel() {
    if (threadIdx.x == 0) { g_bar_cnt = 0; g_bar_phase = 0; }
}

__device__ __forceinline__ void gsync(unsigned &ph) {
    __syncthreads();
    if (threadIdx.x == 0) {
        ph++;
        __threadfence();
        unsigned a = atomicAdd(&g_bar_cnt, 1);
        if (a == NB - 1) {
            atomicExch(&g_bar_cnt, 0);
            __threadfence();
            atomicExch(&g_bar_phase, ph);
        } else {
            while (atomicAdd(&g_bar_phase, 0) < ph) __nanosleep(100);
        }
        __threadfence();
    }
    __syncthreads();
}

__device__ __forceinline__ float gelu_exact(float v) {
    return 0.5f*v*(1.0f + erff(v*0.70710678118654752440f));
}

// ---------------- bf16 split helpers ----------------
__device__ __forceinline__ unsigned pack_hi(float a, float b, float &ra, float &rb) {
    __nv_bfloat16 ha = __float2bfloat16_rn(a);
    __nv_bfloat16 hb = __float2bfloat16_rn(b);
    ra = a - __bfloat162float(ha);
    rb = b - __bfloat162float(hb);
    return ((unsigned)__bfloat16_as_ushort(hb) << 16) | (unsigned)__bfloat16_as_ushort(ha);
}
__device__ __forceinline__ unsigned pack_lo(float a, float b) {
    return ((unsigned)__bfloat16_as_ushort(__float2bfloat16_rn(b)) << 16)
         |  (unsigned)__bfloat16_as_ushort(__float2bfloat16_rn(a));
}
// write a pair (a,b) into u32-plane pair at word index w
__device__ __forceinline__ void wpl2(unsigned* Ph, unsigned* Pl, long w, float a, float b) {
    float ra, rb;
    Ph[w] = pack_hi(a, b, ra, rb);
    Pl[w] = pack_lo(ra, rb);
}
// scalar plane write (epilogues)
__device__ __forceinline__ void wpl(ushort_* Ph, ushort_* Pl, long i, float v) {
    __nv_bfloat16 hb = __float2bfloat16_rn(v);
    Ph[i] = __bfloat16_as_ushort(hb);
    Pl[i] = __bfloat16_as_ushort(__float2bfloat16_rn(v - __bfloat162float(hb)));
}

__device__ __forceinline__ void mma_bf16(float* c,
    unsigned a0, unsigned a1, unsigned a2, unsigned a3, unsigned b0, unsigned b1)
{
    asm volatile(
        "mma.sync.aligned.m16n8k16.row.col.f32.bf16.bf16.f32 "
        "{%0,%1,%2,%3},{%4,%5,%6,%7},{%8,%9},{%0,%1,%2,%3};"
        : "+f"(c[0]), "+f"(c[1]), "+f"(c[2]), "+f"(c[3])
        : "r"(a0), "r"(a1), "r"(a2), "r"(a3), "r"(b0), "r"(b1));
}

__device__ __forceinline__ unsigned smem_u32(const void* p) {
    unsigned a;
    asm("{ .reg .u64 t; cvta.to.shared.u64 t, %1; cvt.u32.u64 %0, t; }" : "=r"(a) : "l"(p));
    return a;
}
__device__ __forceinline__ void cp16(unsigned dst, const void* src) {
    asm volatile("cp.async.cg.shared.global [%0], [%1], 16;" :: "r"(dst), "l"(src) : "memory");
}
#define CP_COMMIT() asm volatile("cp.async.commit_group;" ::: "memory")
#define CP_WAIT1()  asm volatile("cp.async.wait_group 1;" ::: "memory")

// ---------------- epilogue descriptor ----------------
struct Epi {
    float* C;    long sC;  int ldc;     // fp32 row-major out
    float* CTf;  long sCT; int ldct;    // fp32 transposed out
    ushort_ *PRh, *PRl;                 // row planes (ldc, sC)
    ushort_ *PTh, *PTl;                 // transposed planes (ldct, sCT)
    ushort_ *P2h, *P2l;                 // secondary row planes (epi3)
    float* aux;  long sAux;             // fp32 aux in
    const float* aux2;
    float alpha; int epi;
};
__device__ __forceinline__ Epi mkepi() {
    Epi e; e.C=0; e.sC=0; e.ldc=0; e.CTf=0; e.sCT=0; e.ldct=0;
    e.PRh=0; e.PRl=0; e.PTh=0; e.PTl=0; e.P2h=0; e.P2l=0;
    e.aux=0; e.sAux=0; e.aux2=0; e.alpha=1.f; e.epi=0; return e;
}

// ---------------- plane GEMM: C = alpha * A @ B^T (+ epilogue) --------------
// A planes [M][K] (lda), B planes [N][K] (ldb), bf16 hi/lo pairs.
// CTA tile 128x128xk16, 8 warps, 3-stage cp.async pipeline, 1 sync/slab.
__device__ __noinline__ void dgemm_p(float* smf, unsigned smb,
    const ushort_* Ah, const ushort_* Al, long sA, int lda,
    const ushort_* Bh, const ushort_* Bl, long sB, int ldb,
    int nb, int M, int N, int K, const Epi& E, int bofs)
{
    const int tid  = threadIdx.x;
    const int lane = tid & 31, wid = tid >> 5;
    const int wm = wid >> 2, wn = wid & 3;
    const int gq = lane >> 2, tg = lane & 3;
    const int srow = tid >> 1, seg = tid & 1;

    const int tpmN = N >> 7;
    const int tpm  = (M >> 7) * tpmN;
    const int ntile = nb * tpm;
    const int ns = K >> 4;
    int t0 = blockIdx.x - bofs; if (t0 < 0) t0 += NB;

    for (int t = t0; t < ntile; t += NB) {
        const int cb = t / tpm, tt = t - cb*tpm;
        const int bm = tt / tpmN, bn = tt - bm*tpmN;
        const int m0 = bm << 7, n0 = bn << 7;
        const ushort_* pa_h = Ah + (long)cb*sA + (long)(m0+srow)*lda + seg*8;
        const ushort_* pa_l = Al + (long)cb*sA + (long)(m0+srow)*lda + seg*8;
        const ushort_* pb_h = Bh + (long)cb*sB + (long)(n0+srow)*ldb + seg*8;
        const ushort_* pb_l = Bl + (long)cb*sB + (long)(n0+srow)*ldb + seg*8;
        const unsigned dbase = smb + srow*48 + seg*16;

        float acc[4][4][4];
        #pragma unroll
        for (int i=0;i<4;i++)
            #pragma unroll
            for (int j=0;j<4;j++)
                #pragma unroll
                for (int q=0;q<4;q++) acc[i][j][q]=0.f;

        // prologue: slabs 0,1 -> stages 0,1
        #pragma unroll
        for (int p = 0; p < 2; p++) {
            unsigned d = dbase + p*(STW*4);
            cp16(d,           pa_h + p*16);
            cp16(d +   PLW*4, pa_l + p*16);
            cp16(d + 2*PLW*4, pb_h + p*16);
            cp16(d + 3*PLW*4, pb_l + p*16);
            CP_COMMIT();
        }

        for (int i = 0; i < ns; i++) {
            CP_WAIT1();
            __syncthreads();
            if (i + 2 < ns) {                      // refill stage (i+2)%3
                unsigned d = dbase + ((i+2)%3)*(STW*4);
                long ko = (long)(i+2)*16;
                cp16(d,           pa_h + ko);
                cp16(d +   PLW*4, pa_l + ko);
                cp16(d + 2*PLW*4, pb_h + ko);
                cp16(d + 3*PLW*4, pb_l + ko);
            }
            CP_COMMIT();
            const unsigned* SW = (const unsigned*)smf + (i%3)*STW;
            const unsigned* AH = SW;           const unsigned* AL = SW + PLW;
            const unsigned* BH = SW + 2*PLW;   const unsigned* BL = SW + 3*PLW;
            unsigned bh[4][2], bl[4][2];
            #pragma unroll
            for (int nt=0; nt<4; nt++) {
                int bnr = (wn*32 + nt*8 + gq)*SMS;
                bh[nt][0] = BH[bnr + tg]; bh[nt][1] = BH[bnr + tg + 4];
                bl[nt][0] = BL[bnr + tg]; bl[nt][1] = BL[bnr + tg + 4];
            }
            #pragma unroll
            for (int mt=0; mt<4; mt++) {
                int am = (wm*64 + mt*16 + gq)*SMS;
                unsigned ah0=AH[am+tg], ah1=AH[am+8*SMS+tg], ah2=AH[am+tg+4], ah3=AH[am+8*SMS+tg+4];
                unsigned al0=AL[am+tg], al1=AL[am+8*SMS+tg], al2=AL[am+tg+4], al3=AL[am+8*SMS+tg+4];
                #pragma unroll
                for (int nt=0; nt<4; nt++) {
                    mma_bf16(acc[mt][nt], ah0,ah1,ah2,ah3, bh[nt][0],bh[nt][1]);
                    mma_bf16(acc[mt][nt], ah0,ah1,ah2,ah3, bl[nt][0],bl[nt][1]);
                    mma_bf16(acc[mt][nt], al0,al1,al2,al3, bh[nt][0],bh[nt][1]);
                }
            }
        }

        // ---- epilogue ----
        float* C    = E.C   ? E.C   + (long)cb*E.sC  : (float*)0;
        float* CTf  = E.CTf ? E.CTf + (long)cb*E.sCT : (float*)0;
        ushort_* prh = E.PRh ? E.PRh + (long)cb*E.sC  : (ushort_*)0;
        ushort_* prl = E.PRl ? E.PRl + (long)cb*E.sC  : (ushort_*)0;
        ushort_* pth = E.PTh ? E.PTh + (long)cb*E.sCT : (ushort_*)0;
        ushort_* ptl = E.PTl ? E.PTl + (long)cb*E.sCT : (ushort_*)0;
        ushort_* p2h = E.P2h ? E.P2h + (long)cb*E.sC  : (ushort_*)0;
        ushort_* p2l = E.P2l ? E.P2l + (long)cb*E.sC  : (ushort_*)0;
        float* aux  = E.aux ? E.aux + (long)cb*E.sAux : (float*)0;
        #pragma unroll
        for (int mt=0; mt<4; mt++) {
            #pragma unroll
            for (int nt=0; nt<4; nt++) {
                #pragma unroll
                for (int rg=0; rg<4; rg++) {
                    int r = m0 + wm*64 + mt*16 + gq + ((rg>>1)?8:0);
                    int c = n0 + wn*32 + nt*8  + 2*tg + (rg&1);
                    float v = acc[mt][nt][rg];
                    long idx  = (long)r*E.ldc + c;
                    long idxT = (long)c*E.ldct + r;
                    if (E.epi == 0) {
                        float val = E.alpha*v;
                        if (C)   C[idx] = val;
                        if (CTf) CTf[idxT] = val;
                        if (prh) wpl(prh, prl, idx, val);
                        if (pth) wpl(pth, ptl, idxT, val);
                    } else if (E.epi == 1) {
                        float nv = C[idx] + E.alpha*v;
                        C[idx] = nv;
                        if (prh) wpl(prh, prl, idx, nv);
                    } else if (E.epi == 3) {
                        float tv = ((r>>4) > (c>>4)) ? (-ETA)*v : 0.f;
                        wpl(prh, prl, idx, tv);
                        wpl(pth, ptl, idxT, tv);
                        float sa = tv + ((r==c) ? 1.f : 0.f);
                        aux[idx] = sa;
                        wpl(p2h, p2l, idx, sa);
                    } else if (E.epi == 4) {
                        wpl(prh, prl, idx, ((r>>4) >= (c>>4)) ? (-ETA)*v : 0.f);
                    } else if (E.epi == 5) {
                        float val = v + aux[idx];
                        if (C) C[idx] = val;
                        wpl(prh, prl, idx, val);
                    } else if (E.epi == 7) {
                        int b = r/S_, s = r - b*S_;
                        float u = C[idx];
                        C[idx] = gelu_exact(u)*v + g_b1[((long)(s*16+b))*D_ + c] + E.aux2[idx];
                    } else {  // epi 8
                        float val = v + aux[idxT];
                        wpl(pth, ptl, idxT, val);
                    }
                }
            }
        }
        __syncthreads();   // protect stages from next tile's prologue
    }
}

#define USC(p) ((ushort_*)(p))

// ---------------- the mega-kernel ----------------
__global__ void __launch_bounds__(NT, 2)
mega(const float* __restrict__ x, const float* __restrict__ noise,
     const float* __restrict__ alpha1, const float* __restrict__ alpha2,
     const float* __restrict__ Wmap, const float* __restrict__ Wstate,
     const float* __restrict__ Wprobe, const float* __restrict__ Wp1,
     const float* __restrict__ Wp2, float* __restrict__ out)
{
    extern __shared__ __align__(16) float smf[];
    const unsigned smb = smem_u32(smf);
    unsigned ph = 0;
    const long tstep = (long)NB*NT;
    const long gt0 = (long)blockIdx.x*NT + threadIdx.x;

    // ph0: split 5 weights + W master+planes; H = tanh(alpha1*x) -> pH planes
    for (long g = gt0; g < (long)D_*D_/4; g += tstep) {
        long w = g*2;
        float4 v = *(const float4*)(Wmap + g*4);
        *(float4*)(g_W + g*4) = v;
        wpl2(g_pWh,  g_pWl,  w, v.x, v.y); wpl2(g_pWh,  g_pWl,  w+1, v.z, v.w);
        v = *(const float4*)(Wstate + g*4);
        wpl2(g_pWsh, g_pWsl, w, v.x, v.y); wpl2(g_pWsh, g_pWsl, w+1, v.z, v.w);
        v = *(const float4*)(Wprobe + g*4);
        wpl2(g_pWph, g_pWpl, w, v.x, v.y); wpl2(g_pWph, g_pWpl, w+1, v.z, v.w);
        v = *(const float4*)(Wp1 + g*4);
        wpl2(g_pW1h, g_pW1l, w, v.x, v.y); wpl2(g_pW1h, g_pW1l, w+1, v.z, v.w);
        v = *(const float4*)(Wp2 + g*4);
        wpl2(g_pW2h, g_pW2l, w, v.x, v.y); wpl2(g_pW2h, g_pW2l, w+1, v.z, v.w);
    }
    for (long g = gt0; g < (long)R_*D_/4; g += tstep) {
        int d4 = (int)(g % (D_/4)); int r = (int)(g / (D_/4));
        int s = r >> 4, b = r & 15;
        float4 xv = *(const float4*)(x + ((long)b*S_ + s)*D_ + (long)d4*4);
        float4 a  = *(const float4*)(alpha1 + (long)d4*4);
        float hx = tanhf(a.x*xv.x), hy = tanhf(a.y*xv.y);
        float hz = tanhf(a.z*xv.z), hw = tanhf(a.w*xv.w);
        long w = ((long)r*D_ + (long)d4*4)/2;
        wpl2(g_pHh, g_pHl, w, hx, hy); wpl2(g_pHh, g_pHl, w+1, hz, hw);
    }
    gsync(ph);

    // ph1: STATE = H@Ws^T -> b0 fp32 ; PROBE = H@Wp^T -> planes only
    {
        Epi e = mkepi(); e.C = g_b0; e.ldc = D_;
        dgemm_p(smf,smb, USC(g_pHh),USC(g_pHl),0,D_, USC(g_pWsh),USC(g_pWsl),0,D_,
                1, R_,D_,D_, e, 0);
        e = mkepi(); e.PRh = USC(g_pPRh); e.PRl = USC(g_pPRl); e.ldc = D_;
        dgemm_p(smf,smb, USC(g_pHh),USC(g_pHl),0,D_, USC(g_pWph),USC(g_pWpl),0,D_,
                1, R_,D_,D_, e, 0);
    }
    gsync(ph);

    // ph2: TV = STATE + noise -> pTV planes; transposes -> pTVT, pSTT planes
    {
        float (*ts)[33] = (float (*)[33])smf;
        float (*us)[33] = (float (*)[33])(smf + 1088);
        const int rl = threadIdx.x >> 3;
        const int c4 = (threadIdx.x & 7) << 2;
        for (int t = blockIdx.x; t < (R_/32)*(D_/32); t += NB) {
            int rt = t >> 5, ct = t & 31;
            long gr = (long)rt*32 + rl;
            int s = (int)(gr>>4), b = (int)(gr&15);
            float4 st = *(const float4*)(g_b0 + gr*D_ + ct*32 + c4);
            float4 nz = *(const float4*)(noise + ((long)b*S_+s)*D_ + ct*32 + c4);
            float4 tv; tv.x=st.x+nz.x; tv.y=st.y+nz.y; tv.z=st.z+nz.z; tv.w=st.w+nz.w;
            long wrm = (gr*D_ + ct*32 + c4)/2;
            wpl2(g_pTVh, g_pTVl, wrm, tv.x, tv.y); wpl2(g_pTVh, g_pTVl, wrm+1, tv.z, tv.w);
            ts[rl][c4+0]=tv.x; ts[rl][c4+1]=tv.y; ts[rl][c4+2]=tv.z; ts[rl][c4+3]=tv.w;
            us[rl][c4+0]=st.x; us[rl][c4+1]=st.y; us[rl][c4+2]=st.z; us[rl][c4+3]=st.w;
            __syncthreads();
            long wtp = (((long)ct*32 + rl)*R_ + (long)rt*32 + c4)/2;
            wpl2(g_pTVTh, g_pTVTl, wtp,   ts[c4+0][rl], ts[c4+1][rl]);
            wpl2(g_pTVTh, g_pTVTl, wtp+1, ts[c4+2][rl], ts[c4+3][rl]);
            wpl2(g_pSTTh, g_pSTTl, wtp,   us[c4+0][rl], us[c4+1][rl]);
            wpl2(g_pSTTh, g_pSTTl, wtp+1, us[c4+2][rl], us[c4+3][rl]);
            __syncthreads();
        }
    }
    gsync(ph);

    // ph3: Gram -> T/TT/Sa ; P -> Q   (batched)
    {
        Epi e = mkepi(); e.epi = 3; e.ldc = NR; e.sC = NRNR; e.ldct = NR; e.sCT = NRNR;
        e.PRh=USC(g_pTh); e.PRl=USC(g_pTl); e.PTh=USC(g_pTTh); e.PTl=USC(g_pTTl);
        e.P2h=USC(g_pSah); e.P2l=USC(g_pSal); e.aux=g_Sa; e.sAux=NRNR;
        dgemm_p(smf,smb, USC(g_pTVh),USC(g_pTVl),(long)NR*D_,D_,
                USC(g_pTVh),USC(g_pTVl),(long)NR*D_,D_, NCH,NR,NR,D_, e, 0);
        e = mkepi(); e.epi = 4; e.ldc = NR; e.sC = NRNR;
        e.PRh=USC(g_pQh); e.PRl=USC(g_pQl);
        dgemm_p(smf,smb, USC(g_pPRh),USC(g_pPRl),(long)NR*D_,D_,
                USC(g_pTVh),USC(g_pTVl),(long)NR*D_,D_, NCH,NR,NR,D_, e, 148);
    }
    gsync(ph);

    // Minv chain (batched; exact: T^16 = 0)
    {
        Epi e = mkepi(); e.ldc=NR; e.sC=NRNR; e.ldct=NR; e.sCT=NRNR;   // sq1: T2
        e.PRh=USC(g_pT2h); e.PRl=USC(g_pT2l); e.PTh=USC(g_pCT2h); e.PTl=USC(g_pCT2l);
        dgemm_p(smf,smb, USC(g_pTh),USC(g_pTl),NRNR,NR, USC(g_pTTh),USC(g_pTTl),NRNR,NR,
                NCH,NR,NR,NR, e, 0);
    }
    gsync(ph);
    {
        Epi e = mkepi(); e.epi=5; e.C=g_Sb; e.ldc=NR; e.sC=NRNR;       // cb1: Sb=Sa(I+T2)
        e.PRh=USC(g_pSbh); e.PRl=USC(g_pSbl); e.aux=g_Sa; e.sAux=NRNR;
        dgemm_p(smf,smb, USC(g_pSah),USC(g_pSal),NRNR,NR, USC(g_pCT2h),USC(g_pCT2l),NRNR,NR,
                NCH,NR,NR,NR, e, 0);
        e = mkepi(); e.ldc=NR; e.sC=NRNR; e.ldct=NR; e.sCT=NRNR;       // sq2: T4 -> pT,pTT
        e.PRh=USC(g_pTh); e.PRl=USC(g_pTl); e.PTh=USC(g_pTTh); e.PTl=USC(g_pTTl);
        dgemm_p(smf,smb, USC(g_pT2h),USC(g_pT2l),NRNR,NR, USC(g_pCT2h),USC(g_pCT2l),NRNR,NR,
                NCH,NR,NR,NR, e, 148);
    }
    gsync(ph);
    {
        Epi e = mkepi(); e.epi=5; e.C=g_Sa; e.ldc=NR; e.sC=NRNR;       // cb2: Sa=Sb(I+T4)
        e.PRh=USC(g_pSah); e.PRl=USC(g_pSal); e.aux=g_Sb; e.sAux=NRNR;
        dgemm_p(smf,smb, USC(g_pSbh),USC(g_pSbl),NRNR,NR, USC(g_pTTh),USC(g_pTTl),NRNR,NR,
                NCH,NR,NR,NR, e, 0);
        e = mkepi(); e.ldc=NR; e.ldct=NR; e.sCT=NRNR;                  // sq3: T8^T -> pCT2
        e.PTh=USC(g_pCT2h); e.PTl=USC(g_pCT2l);
        dgemm_p(smf,smb, USC(g_pTh),USC(g_pTl),NRNR,NR, USC(g_pTTh),USC(g_pTTl),NRNR,NR,
                NCH,NR,NR,NR, e, 148);
    }
    gsync(ph);
    {
        Epi e = mkepi(); e.epi=5; e.ldc=NR; e.sC=NRNR;                 // cb3: Minv -> pSb
        e.PRh=USC(g_pSbh); e.PRl=USC(g_pSbl); e.aux=g_Sa; e.sAux=NRNR;
        dgemm_p(smf,smb, USC(g_pSah),USC(g_pSal),NRNR,NR, USC(g_pCT2h),USC(g_pCT2l),NRNR,NR,
                NCH,NR,NR,NR, e, 0);
    }
    gsync(ph);

    // MT = Minv@TV -> planes ; E0^T = -(Minv@STATE)^T -> g_ET fp32
    {
        Epi e = mkepi(); e.PRh=USC(g_pMTh); e.PRl=USC(g_pMTl); e.ldc=D_; e.sC=(long)NR*D_;
        dgemm_p(smf,smb, USC(g_pSbh),USC(g_pSbl),NRNR,NR,
                USC(g_pTVTh),USC(g_pTVTl),(long)NR,R_, NCH,NR,D_,NR, e, 0);
        e = mkepi(); e.alpha=-1.f; e.CTf=g_ET; e.ldct=R_; e.sCT=NR; e.ldc=D_;
        dgemm_p(smf,smb, USC(g_pSbh),USC(g_pSbl),NRNR,NR,
                USC(g_pSTTh),USC(g_pSTTl),(long)NR,R_, NCH,NR,D_,NR, e, 0);
    }
    gsync(ph);

    // Sequential W-dependent loop: 2 phases per chunk
    for (int c = 0; c < NCH; c++) {
        {   // phA: E_c = MT_c@W^T + E0_c -> pET planes ; RDbase_c = PROBE_c@W^T -> b1
            Epi e = mkepi(); e.epi=8; e.ldc=D_; e.ldct=R_;
            e.PTh=USC(g_pETh) + (long)c*NR; e.PTl=USC(g_pETl) + (long)c*NR;
            e.aux=g_ET + (long)c*NR;
            dgemm_p(smf,smb, USC(g_pMTh)+(long)c*NR*D_, USC(g_pMTl)+(long)c*NR*D_, 0,D_,
                    USC(g_pWh),USC(g_pWl),0,D_, 1,NR,D_,D_, e, 0);
            e = mkepi(); e.C=g_b1+(long)c*NR*D_; e.ldc=D_;
            dgemm_p(smf,smb, USC(g_pPRh)+(long)c*NR*D_, USC(g_pPRl)+(long)c*NR*D_, 0,D_,
                    USC(g_pWh),USC(g_pWl),0,D_, 1,NR,D_,D_, e, 16);
        }
        gsync(ph);
        {   // phB: W += -eta * E_c^T @ TV_c ; re-split W planes
            Epi e = mkepi(); e.epi=1; e.alpha=-ETA; e.C=g_W; e.ldc=D_;
            e.PRh=USC(g_pWh); e.PRl=USC(g_pWl);
            dgemm_p(smf,smb, USC(g_pETh)+(long)c*NR, USC(g_pETl)+(long)c*NR, 0,R_,
                    USC(g_pTVTh)+(long)c*NR, USC(g_pTVTl)+(long)c*NR, 0,R_,
                    1,D_,D_,NR, e, 0);
        }
        gsync(ph);
    }

    // batched: RD += Q_c @ E_c
    {
        Epi e = mkepi(); e.epi=1; e.C=g_b1; e.sC=(long)NR*D_; e.ldc=D_;
        dgemm_p(smf,smb, USC(g_pQh),USC(g_pQl),NRNR,NR,
                USC(g_pETh),USC(g_pETl),(long)NR,R_, NCH,NR,D_,NR, e, 0);
    }
    gsync(ph);

    // H2 = tanh(alpha2*(RD[perm] + x)) -> pH planes (reuse)
    for (long g = gt0; g < (long)R_*D_/4; g += tstep) {
        int d4 = (int)(g % (D_/4)); int r = (int)(g / (D_/4));
        int b = r / S_, s = r - b*S_;
        float4 rd = *(const float4*)(g_b1 + ((long)(s*16+b))*D_ + (long)d4*4);
        float4 xv = *(const float4*)(x + (long)r*D_ + (long)d4*4);
        float4 a2 = *(const float4*)(alpha2 + (long)d4*4);
        float hx = tanhf(a2.x*(rd.x+xv.x)), hy = tanhf(a2.y*(rd.y+xv.y));
        float hz = tanhf(a2.z*(rd.z+xv.z)), hw = tanhf(a2.w*(rd.w+xv.w));
        long w = ((long)r*D_ + (long)d4*4)/2;
        wpl2(g_pHh, g_pHl, w, hx, hy); wpl2(g_pHh, g_pHl, w+1, hz, hw);
    }
    gsync(ph);

    // U = H2@Wp1^T -> out
    {
        Epi e = mkepi(); e.C=out; e.ldc=D_;
        dgemm_p(smf,smb, USC(g_pHh),USC(g_pHl),0,D_, USC(g_pW1h),USC(g_pW1l),0,D_,
                1,R_,D_,D_, e, 0);
    }
    gsync(ph);

    // out = gelu(U) * (H2@Wp2^T) + RD[perm] + x
    {
        Epi e = mkepi(); e.epi=7; e.C=out; e.ldc=D_; e.aux2=x;
        dgemm_p(smf,smb, USC(g_pHh),USC(g_pHl),0,D_, USC(g_pW2h),USC(g_pW2l),0,D_,
                1,R_,D_,D_, e, 0);
    }
}

extern "C" void kernel_launch(void* const* d_in, const int* in_sizes, int n_in,
                              void* d_out, int out_size) {
    const float* x       = (const float*)d_in[0];
    const float* noise   = (const float*)d_in[1];
    const float* alpha1  = (const float*)d_in[2];
    const float* alpha2  = (const float*)d_in[3];
    const float* W_map   = (const float*)d_in[4];
    const float* W_state = (const float*)d_in[5];
    const float* W_probe = (const float*)d_in[6];
    const float* W_p1    = (const float*)d_in[7];
    const float* W_p2    = (const float*)d_in[8];
    float* out = (float*)d_out;

    cudaFuncSetAttribute(mega, cudaFuncAttributeMaxDynamicSharedMemorySize, DSMEM);
    reset_kernel<<<1, 32>>>();
    mega<<<NB, NT, DSMEM>>>(x, noise, alpha1, alpha2, W_map, W_state, W_probe,
                            W_p1, W_p2, out);
}

// round 16
// speedup vs baseline: 1.4323x; 1.4323x over previous
#include <cuda_runtime.h>
#include <cuda_bf16.h>
#include <math.h>

#define B_ 16
#define S_ 1024
#define D_ 1024
#define R_ (B_*S_)           // 16384 rows (step-major: r = s*16 + b)
#define NR 256               // rows per chunk (16 steps x 16 batch)
#define NCH 64               // chunks
#define NRNR ((long)NR*NR)
#define DD   ((long)D_*D_)
#define ETA (0.01f * (2.0f/16384.0f))
#define NB 296               // persistent blocks (2/SM)
#define NT 256
#define STGW 20              // fp32 stage row stride (floats)
#define DSMEM 57344          // 2 fp32 stages (40KB) + 4 frag planes (16KB)

// ---------------- fp32 scratch (~1.4 GB static; proven-safe scale) ---------
static __device__ float g_b0 [R_*D_];        // STATE -> TV -> H2
static __device__ float g_b1 [R_*D_];        // H -> RDbase -> RD
static __device__ float g_TVT[D_*R_];        // TV^T  [D][R]
static __device__ float g_STT[D_*R_];        // STATE^T [D][R]
static __device__ float g_MT [R_*D_];        // Minv@TV row-major, batched
static __device__ float g_MTT[D_*R_];        // (Minv@TV)^T
static __device__ float g_ET [D_*R_];        // E0^T, then E^T
static __device__ float g_Wseq[(NCH+1)*D_*D_]; // W_0..W_64
static __device__ float g_AT [NCH*D_*D_];    // -eta * P_c^T   per chunk
static __device__ float g_K  [NCH*D_*D_];    // -eta * E0^T TV per chunk
static __device__ float g_T  [NCH*NR*NR];
static __device__ float g_TT [NCH*NR*NR];
static __device__ float g_T2 [NCH*NR*NR];
static __device__ float g_CT2[NCH*NR*NR];
static __device__ float g_Sa [NCH*NR*NR];
static __device__ float g_Sb [NCH*NR*NR];    // final Minv
static __device__ float g_Q  [NCH*NR*NR];

static __device__ unsigned g_bar_cnt;
static __device__ unsigned g_bar_phase;

__global__ void reset_kernel() {
    if (threadIdx.x == 0) { g_bar_cnt = 0; g_bar_phase = 0; }
}

__device__ __forceinline__ void gsync(unsigned &ph) {
    __syncthreads();
    if (threadIdx.x == 0) {
        ph++;
        __threadfence();
        unsigned a = atomicAdd(&g_bar_cnt, 1);
        if (a == NB - 1) {
            atomicExch(&g_bar_cnt, 0);
            __threadfence();
            atomicExch(&g_bar_phase, ph);
        } else {
            while (atomicAdd(&g_bar_phase, 0) < ph) __nanosleep(100);
        }
        __threadfence();
    }
    __syncthreads();
}

__device__ __forceinline__ float gelu_exact(float v) {
    return 0.5f*v*(1.0f + erff(v*0.70710678118654752440f));
}

// ---------------- cheap bf16 hi/lo split ----------------
// hi = RN-bf16x2(a,b); residual exact in fp32; lo = RN-bf16x2(residuals)
__device__ __forceinline__ unsigned cvt2(float a, float b) {
    unsigned r;
    asm("cvt.rn.bf16x2.f32 %0, %1, %2;" : "=r"(r) : "f"(b), "f"(a));
    return r;
}
__device__ __forceinline__ unsigned split2(float a, float b, unsigned &lo) {
    unsigned h = cvt2(a, b);
    float ha = __uint_as_float(h << 16);
    float hb = __uint_as_float(h & 0xFFFF0000u);
    lo = cvt2(a - ha, b - hb);
    return h;
}

__device__ __forceinline__ void mma_bf16(float* c,
    unsigned a0, unsigned a1, unsigned a2, unsigned a3, unsigned b0, unsigned b1)
{
    asm volatile(
        "mma.sync.aligned.m16n8k16.row.col.f32.bf16.bf16.f32 "
        "{%0,%1,%2,%3},{%4,%5,%6,%7},{%8,%9},{%0,%1,%2,%3};"
        : "+f"(c[0]), "+f"(c[1]), "+f"(c[2]), "+f"(c[3])
        : "r"(a0), "r"(a1), "r"(a2), "r"(a3), "r"(b0), "r"(b1));
}

__device__ __forceinline__ unsigned smem_u32(const void* p) {
    unsigned a;
    asm("{ .reg .u64 t; cvta.to.shared.u64 t, %1; cvt.u32.u64 %0, t; }" : "=r"(a) : "l"(p));
    return a;
}
__device__ __forceinline__ void cp16(unsigned dst, const void* src) {
    asm volatile("cp.async.cg.shared.global [%0], [%1], 16;" :: "r"(dst), "l"(src) : "memory");
}
#define CP_COMMIT() asm volatile("cp.async.commit_group;" ::: "memory")
#define CP_WAIT1()  asm volatile("cp.async.wait_group 1;" ::: "memory")

// ---------------- bf16-split NT GEMM, frag-major planes ---------------------
// C[M][N] = alpha * A[M][K] @ B[N][K]^T (+ epilogue). CTA 128x128xk16, 8 warps.
// epi: 0: C=alpha*acc and/or CTf=alpha*acc
//      1: C += alpha*acc
//      3: T=-eta*strictBL(acc) -> C and CTf; aux = T + I
//      4: C = -eta*inclBL(acc)
//      5: C = acc + aux[idx]
//      7: C = gelu(C)*acc + RD[perm] + aux2[idx]
//      8: CTf[idxT] += acc
//      9: C = alpha*acc + aux[idx] + aux2[idx]        (W recursion)
__device__ __noinline__ void dgemm_nt(float* smf, unsigned smb,
    const float* __restrict__ A0, long sA, int lda,
    const float* __restrict__ B0, long sB, int ldb,
    float* C0, long sC, int ldc,
    float* CT0, long sCT, int ldct,
    int nb, int M, int N, int K,
    float alpha, int epi,
    float* aux, long sAux, const float* __restrict__ aux2, int bofs)
{
    unsigned* PH = (unsigned*)smf + 10240;          // frag planes: AH AL BH BL
    unsigned* AHp = PH;       unsigned* ALp = PH + 1024;
    unsigned* BHp = PH + 2048; unsigned* BLp = PH + 3072;

    const int tid  = threadIdx.x;
    const int lane = tid & 31, wid = tid >> 5;
    const int wm = wid >> 2, wn = wid & 3;
    const int gq = lane >> 2, tg = lane & 3;

    // cp.async mapping
    const int crow = tid >> 2;
    const int ko4  = (tid & 3) << 2;
    const int w0b  = (crow*STGW + ko4)*4;
    const int w1b  = w0b + 64*STGW*4;

    // convert mapping
    const int ar0 = ((tid >> 5) << 4) + gq;         // A rows ar0, ar0+8
    const int brow = ((tid >> 4) << 3) + ((tid & 15) >> 1);
    const int ba2  = (tid & 1) * 2;

    const int tpmN = N >> 7;
    const int tpm  = (M >> 7) * tpmN;
    const int ntile = nb * tpm;
    const int ns = K >> 4;
    int t0 = blockIdx.x - bofs; if (t0 < 0) t0 += NB;

    for (int t = t0; t < ntile; t += NB) {
        const int cb = t / tpm, tt = t - cb*tpm;
        const int bm = tt / tpmN, bn = tt - bm*tpmN;
        const int m0 = bm << 7, n0 = bn << 7;
        const float* A = A0 + (long)cb*sA;
        const float* B = B0 + (long)cb*sB;
        const float* sA0 = A + (long)(m0 + crow)*lda + ko4;
        const float* sA1 = A + (long)(m0 + 64 + crow)*lda + ko4;
        const float* sB0 = B + (long)(n0 + crow)*ldb + ko4;
        const float* sB1 = B + (long)(n0 + 64 + crow)*ldb + ko4;

        float acc[4][4][4];
        #pragma unroll
        for (int i=0;i<4;i++)
            #pragma unroll
            for (int j=0;j<4;j++)
                #pragma unroll
                for (int q=0;q<4;q++) acc[i][j][q]=0.f;

        // prologue: slabs 0,1 -> stages 0,1
        #pragma unroll
        for (int p = 0; p < 2; p++) {
            unsigned oA = smb + p*20480, oB = oA + 10240;
            cp16(oA + w0b, sA0 + p*16); cp16(oA + w1b, sA1 + p*16);
            cp16(oB + w0b, sB0 + p*16); cp16(oB + w1b, sB1 + p*16);
            CP_COMMIT();
        }

        for (int i = 0; i < ns; i++) {
            const int st = i & 1;
            CP_WAIT1();
            __syncthreads();
            // ---- convert stage -> frag-major bf16 planes (1 STS.128 each) ----
            {
                const float* SA = smf + st*5120;
                const float* SB = SA + 2560;
                const float* p0 = SA + ar0*STGW + 2*tg;
                const float* p1 = p0 + 8*STGW;
                float2 a00 = *(const float2*)p0;
                float2 a01 = *(const float2*)(p0 + 8);
                float2 a10 = *(const float2*)p1;
                float2 a11 = *(const float2*)(p1 + 8);
                uint4 h, l;
                h.x = split2(a00.x, a00.y, l.x);
                h.y = split2(a10.x, a10.y, l.y);
                h.z = split2(a01.x, a01.y, l.z);
                h.w = split2(a11.x, a11.y, l.w);
                *(uint4*)(AHp + 4*tid) = h;
                *(uint4*)(ALp + 4*tid) = l;
                const float* q = SB + brow*STGW + 2*ba2;
                float4 b0 = *(const float4*)q;
                float4 b1 = *(const float4*)(q + 8);
                h.x = split2(b0.x, b0.y, l.x);
                h.y = split2(b1.x, b1.y, l.y);
                h.z = split2(b0.z, b0.w, l.z);
                h.w = split2(b1.z, b1.w, l.w);
                *(uint4*)(BHp + 4*tid) = h;
                *(uint4*)(BLp + 4*tid) = l;
            }
            __syncthreads();
            // refill this stage with slab i+2
            if (i + 2 < ns) {
                const int ks = (i + 2) << 4;
                unsigned oA = smb + st*20480, oB = oA + 10240;
                cp16(oA + w0b, sA0 + ks); cp16(oA + w1b, sA1 + ks);
                cp16(oB + w0b, sB0 + ks); cp16(oB + w1b, sB1 + ks);
            }
            CP_COMMIT();
            // ---- one k16 slab: 16 vector LDS + 48 MMAs ----
            uint2 bh[4], bl[4];
            #pragma unroll
            for (int nt=0; nt<4; nt++) {
                int bo = ((wn*4 + nt) << 6) + (lane << 1);
                bh[nt] = *(const uint2*)(BHp + bo);
                bl[nt] = *(const uint2*)(BLp + bo);
            }
            #pragma unroll
            for (int mt=0; mt<4; mt++) {
                int ao = ((wm*4 + mt) << 7) + (lane << 2);
                uint4 ah = *(const uint4*)(AHp + ao);
                uint4 al = *(const uint4*)(ALp + ao);
                #pragma unroll
                for (int nt=0; nt<4; nt++) {
                    mma_bf16(acc[mt][nt], ah.x,ah.y,ah.z,ah.w, bh[nt].x,bh[nt].y);
                    mma_bf16(acc[mt][nt], ah.x,ah.y,ah.z,ah.w, bl[nt].x,bl[nt].y);
                    mma_bf16(acc[mt][nt], al.x,al.y,al.z,al.w, bh[nt].x,bh[nt].y);
                }
            }
        }

        // ---- epilogue over fragment (r,c) mapping ----
        float* C    = C0  ? C0  + (long)cb*sC   : (float*)0;
        float* CTf  = CT0 ? CT0 + (long)cb*sCT  : (float*)0;
        float* auxc = aux ? aux + (long)cb*sAux : (float*)0;
        #pragma unroll
        for (int mt=0; mt<4; mt++) {
            #pragma unroll
            for (int nt=0; nt<4; nt++) {
                #pragma unroll
                for (int rg=0; rg<4; rg++) {
                    int r = m0 + wm*64 + mt*16 + gq + ((rg>>1)?8:0);
                    int c = n0 + wn*32 + nt*8  + 2*tg + (rg&1);
                    float v = acc[mt][nt][rg];
                    long idx  = (long)r*ldc + c;
                    long idxT = (long)c*ldct + r;
                    if (epi == 0) {
                        float val = alpha*v;
                        if (C)   C[idx] = val;
                        if (CTf) CTf[idxT] = val;
                    } else if (epi == 1) {
                        C[idx] += alpha*v;
                    } else if (epi == 3) {
                        float tv = ((r>>4) > (c>>4)) ? (-ETA)*v : 0.f;
                        C[idx] = tv;
                        CTf[idxT] = tv;
                        auxc[idx] = tv + ((r==c) ? 1.f : 0.f);
                    } else if (epi == 4) {
                        C[idx] = ((r>>4) >= (c>>4)) ? (-ETA)*v : 0.f;
                    } else if (epi == 5) {
                        C[idx] = v + auxc[idx];
                    } else if (epi == 7) {
                        int b = r/S_, s = r - b*S_;
                        float u = C[idx];
                        C[idx] = gelu_exact(u)*v + g_b1[((long)(s*16+b))*D_ + c] + aux2[idx];
                    } else if (epi == 8) {
                        CTf[idxT] += v;
                    } else { // epi == 9: W recursion
                        C[idx] = alpha*v + auxc[idx] + aux2[idx];
                    }
                }
            }
        }
    }
}

#define DG(A0,sA,lda,B0,sB,ldb,C0,sC,ldc,CT0,sCT,ldct,nb,M,N,K,al,epi,aux,sAux,aux2,bofs) \
    dgemm_nt(smf, smb, A0,sA,lda, B0,sB,ldb, C0,sC,ldc, CT0,sCT,ldct, \
             nb,M,N,K, al,epi, aux,sAux, aux2, bofs)
#define NP (float*)0
#define NCP (const float*)0

// ---------------- the mega-kernel ----------------
__global__ void __launch_bounds__(NT, 2)
mega(const float* __restrict__ x, const float* __restrict__ noise,
     const float* __restrict__ alpha1, const float* __restrict__ alpha2,
     const float* __restrict__ Wmap, const float* __restrict__ Wstate,
     const float* __restrict__ Wprobe, const float* __restrict__ Wp1,
     const float* __restrict__ Wp2, float* __restrict__ out)
{
    extern __shared__ __align__(16) float smf[];
    const unsigned smb = smem_u32(smf);
    unsigned ph = 0;
    const long tstep = (long)NB*NT;
    const long gt0 = (long)blockIdx.x*NT + threadIdx.x;

    // ph0: W_0 = Wmap ; H = tanh(alpha1*x) (step-major permuted) -> b1
    for (long g = gt0; g < (long)D_*D_/4; g += tstep)
        *(float4*)(g_Wseq + g*4) = *(const float4*)(Wmap + g*4);
    for (long g = gt0; g < (long)R_*D_/4; g += tstep) {
        int d4 = (int)(g % (D_/4)); int r = (int)(g / (D_/4));
        int s = r >> 4, b = r & 15;
        float4 xv = *(const float4*)(x + ((long)b*S_ + s)*D_ + (long)d4*4);
        float4 a  = *(const float4*)(alpha1 + (long)d4*4);
        float4 h;
        h.x = tanhf(a.x*xv.x); h.y = tanhf(a.y*xv.y);
        h.z = tanhf(a.z*xv.z); h.w = tanhf(a.w*xv.w);
        *(float4*)(g_b1 + (long)r*D_ + (long)d4*4) = h;
    }
    gsync(ph);

    // ph1: STATE = H@Ws^T -> b0 ; PROBE = H@Wp^T -> out
    DG(g_b1,0,D_, Wstate,0,D_, g_b0,0,D_, NP,0,0, 1, R_,D_,D_, 1.f, 0, NP,0, NCP, 0);
    DG(g_b1,0,D_, Wprobe,0,D_, out, 0,D_, NP,0,0, 1, R_,D_,D_, 1.f, 0, NP,0, NCP, 0);
    gsync(ph);

    // ph2: TV = STATE + noise (in place) ; TVT and STT transposes (32x32 tiles)
    {
        float (*ts)[33] = (float (*)[33])smf;
        float (*us)[33] = (float (*)[33])(smf + 1088);
        const int rl = threadIdx.x >> 3;
        const int c4 = (threadIdx.x & 7) << 2;
        for (int t = blockIdx.x; t < (R_/32)*(D_/32); t += NB) {
            int rt = t >> 5, ct = t & 31;
            long gr = (long)rt*32 + rl;
            int s = (int)(gr>>4), b = (int)(gr&15);
            float4 st = *(const float4*)(g_b0 + gr*D_ + ct*32 + c4);
            float4 nz = *(const float4*)(noise + ((long)b*S_+s)*D_ + ct*32 + c4);
            us[rl][c4+0]=st.x; us[rl][c4+1]=st.y; us[rl][c4+2]=st.z; us[rl][c4+3]=st.w;
            st.x+=nz.x; st.y+=nz.y; st.z+=nz.z; st.w+=nz.w;
            *(float4*)(g_b0 + gr*D_ + ct*32 + c4) = st;
            ts[rl][c4+0]=st.x; ts[rl][c4+1]=st.y; ts[rl][c4+2]=st.z; ts[rl][c4+3]=st.w;
            __syncthreads();
            float4 o;
            o.x = ts[c4+0][rl]; o.y = ts[c4+1][rl];
            o.z = ts[c4+2][rl]; o.w = ts[c4+3][rl];
            *(float4*)(g_TVT + ((long)ct*32 + rl)*R_ + (long)rt*32 + c4) = o;
            o.x = us[c4+0][rl]; o.y = us[c4+1][rl];
            o.z = us[c4+2][rl]; o.w = us[c4+3][rl];
            *(float4*)(g_STT + ((long)ct*32 + rl)*R_ + (long)rt*32 + c4) = o;
            __syncthreads();
        }
    }
    gsync(ph);

    // ph3 (batched): Gram -> T/TT/Sa ; P -> Q
    DG(g_b0,(long)NR*D_,D_, g_b0,(long)NR*D_,D_, g_T,NRNR,NR, g_TT,NRNR,NR,
       NCH, NR,NR,D_, 1.f, 3, g_Sa,NRNR, NCP, 0);
    DG(out,(long)NR*D_,D_, g_b0,(long)NR*D_,D_, g_Q,NRNR,NR, NP,0,0,
       NCH, NR,NR,D_, 1.f, 4, NP,0, NCP, 148);
    gsync(ph);

    // Minv = (I+T)(I+T^2)(I+T^4)(I+T^8), batched (exact: T^16 = 0)
    DG(g_T,NRNR,NR, g_TT,NRNR,NR, g_T2,NRNR,NR, g_CT2,NRNR,NR,
       NCH, NR,NR,NR, 1.f, 0, NP,0, NCP, 0);                              // T2 pair
    gsync(ph);
    DG(g_Sa,NRNR,NR, g_CT2,NRNR,NR, g_Sb,NRNR,NR, NP,0,0,
       NCH, NR,NR,NR, 1.f, 5, g_Sa,NRNR, NCP, 0);                         // Sb=Sa(I+T2)
    DG(g_T2,NRNR,NR, g_CT2,NRNR,NR, g_T,NRNR,NR, g_TT,NRNR,NR,
       NCH, NR,NR,NR, 1.f, 0, NP,0, NCP, 148);                            // T4 pair
    gsync(ph);
    DG(g_Sb,NRNR,NR, g_TT,NRNR,NR, g_Sa,NRNR,NR, NP,0,0,
       NCH, NR,NR,NR, 1.f, 5, g_Sb,NRNR, NCP, 0);                         // Sa=Sb(I+T4)
    DG(g_T,NRNR,NR, g_TT,NRNR,NR, NP,0,0, g_CT2,NRNR,NR,
       NCH, NR,NR,NR, 1.f, 0, NP,0, NCP, 148);                            // T8^T
    gsync(ph);
    DG(g_Sa,NRNR,NR, g_CT2,NRNR,NR, g_Sb,NRNR,NR, NP,0,0,
       NCH, NR,NR,NR, 1.f, 5, g_Sa,NRNR, NCP, 0);                         // Minv in Sb
    gsync(ph);

    // MT = Minv@TV -> g_MT + g_MTT ; E0^T = -(Minv@STATE)^T -> g_ET
    DG(g_Sb,NRNR,NR, g_TVT,(long)NR,R_, g_MT,(long)NR*D_,D_, g_MTT,(long)NR,R_,
       NCH, NR,D_,NR, 1.f, 0, NP,0, NCP, 0);
    DG(g_Sb,NRNR,NR, g_STT,(long)NR,R_, NP,0,0, g_ET,(long)NR,R_,
       NCH, NR,D_,NR, -1.f, 0, NP,0, NCP, 148);
    gsync(ph);

    // AT_c = -eta * TV^T@MT  (P_c^T scaled) ; K_c = -eta * E0^T@TV   (batched)
    DG(g_TVT,(long)NR,R_, g_MTT,(long)NR,R_, g_AT,DD,D_, NP,0,0,
       NCH, D_,D_,NR, -ETA, 0, NP,0, NCP, 0);
    DG(g_ET,(long)NR,R_, g_TVT,(long)NR,R_, g_K,DD,D_, NP,0,0,
       NCH, D_,D_,NR, -ETA, 0, NP,0, NCP, 148);
    gsync(ph);

    // Sequential W recursion: ONE GEMM + ONE barrier per chunk
    // W_{c+1} = W_c @ AT_c^T(+) + W_c + K_c
    for (int c = 0; c < NCH; c++) {
        DG(g_Wseq + (long)c*DD, 0, D_, g_AT + (long)c*DD, 0, D_,
           g_Wseq + (long)(c+1)*DD, 0, D_, NP,0,0,
           1, D_,D_,D_, 1.f, 9, g_K + (long)c*DD, 0, g_Wseq + (long)c*DD, 0);
        gsync(ph);
    }

    // batched: E^T = MT@W_c^T + E0^T (RMW into g_ET) ; RDbase = PROBE@W_c^T -> b1
    DG(g_MT,(long)NR*D_,D_, g_Wseq,DD,D_, NP,0,0, g_ET,(long)NR,R_,
       NCH, NR,D_,D_, 1.f, 8, NP,0, NCP, 0);
    DG(out,(long)NR*D_,D_, g_Wseq,DD,D_, g_b1,(long)NR*D_,D_, NP,0,0,
       NCH, NR,D_,D_, 1.f, 0, NP,0, NCP, 148);
    gsync(ph);

    // batched: RD += Q_c @ E_c
    DG(g_Q,NRNR,NR, g_ET,(long)NR,R_, g_b1,(long)NR*D_,D_, NP,0,0,
       NCH, NR,D_,NR, 1.f, 1, NP,0, NCP, 0);
    gsync(ph);

    // H2 = tanh(alpha2*(RD[perm] + x)) -> b0 (row-major r = b*S+s)
    for (long g = gt0; g < (long)R_*D_/4; g += tstep) {
        int d4 = (int)(g % (D_/4)); int r = (int)(g / (D_/4));
        int b = r / S_, s = r - b*S_;
        float4 rd = *(const float4*)(g_b1 + ((long)(s*16+b))*D_ + (long)d4*4);
        float4 xv = *(const float4*)(x + (long)r*D_ + (long)d4*4);
        float4 a2 = *(const float4*)(alpha2 + (long)d4*4);
        float4 h2;
        h2.x = tanhf(a2.x*(rd.x+xv.x)); h2.y = tanhf(a2.y*(rd.y+xv.y));
        h2.z = tanhf(a2.z*(rd.z+xv.z)); h2.w = tanhf(a2.w*(rd.w+xv.w));
        *(float4*)(g_b0 + (long)r*D_ + (long)d4*4) = h2;
    }
    gsync(ph);

    // U = H2@Wp1^T -> out
    DG(g_b0,0,D_, Wp1,0,D_, out,0,D_, NP,0,0, 1, R_,D_,D_, 1.f, 0, NP,0, NCP, 0);
    gsync(ph);

    // out = gelu(U) * (H2@Wp2^T) + RD[perm] + x
    DG(g_b0,0,D_, Wp2,0,D_, out,0,D_, NP,0,0, 1, R_,D_,D_, 1.f, 7, NP,0, x, 0);
}

extern "C" void kernel_launch(void* const* d_in, const int* in_sizes, int n_in,
                              void* d_out, int out_size) {
    const float* x       = (const float*)d_in[0];
    const float* noise   = (const float*)d_in[1];
    const float* alpha1  = (const float*)d_in[2];
    const float* alpha2  = (const float*)d_in[3];
    const float* W_map   = (const float*)d_in[4];
    const float* W_state = (const float*)d_in[5];
    const float* W_probe = (const float*)d_in[6];
    const float* W_p1    = (const float*)d_in[7];
    const float* W_p2    = (const float*)d_in[8];
    float* out = (float*)d_out;

    cudaFuncSetAttribute(mega, cudaFuncAttributeMaxDynamicSharedMemorySize, DSMEM);
    reset_kernel<<<1, 32>>>();
    mega<<<NB, NT, DSMEM>>>(x, noise, alpha1, alpha2, W_map, W_state, W_probe,
                            W_p1, W_p2, out);
}